// round 15
// baseline (speedup 1.0000x reference)
#include <cuda_runtime.h>
#include <cstdlib>
#include <cstdint>

#define NUM_SEG   32
#define MUL       128
#define D         3
#define NUM_PATHS 64
#define SEG_ELEMS (MUL * D)              // 384 floats per segment
#define SEG_BYTES (SEG_ELEMS * 4)        // 1536 bytes
#define ROW_ELEMS (NUM_SEG * SEG_ELEMS)  // 12288 floats per batch row
#define STAGES    4

__device__ __forceinline__ void cpasync16(uint32_t dst, const void* src) {
    asm volatile("cp.async.cg.shared.global [%0], [%1], 16;\n"
                 :: "r"(dst), "l"(src) : "memory");
}
#define CP_COMMIT() asm volatile("cp.async.commit_group;\n" ::: "memory")
#define CP_WAIT3()  asm volatile("cp.async.wait_group 3;\n" ::: "memory")

__global__ __launch_bounds__(128, 7)     // ~70 regs; smem-limited 7 CTAs/SM
void ftp3_main(const float* __restrict__ x0,
               const float* __restrict__ x1,
               const float* __restrict__ coeff,
               const int*   __restrict__ idx0,
               const int*   __restrict__ idx1,
               const int*   __restrict__ idx2,
               float*       __restrict__ out)
{
    // Per-warp 4-stage ring: one full 1536B segment slice per stage.
    __shared__ __align__(16) float ring[4][STAGES][SEG_ELEMS];
    __shared__ __align__(16) float M[NUM_PATHS * 12];
    __shared__ int s_idx2[NUM_PATHS];
    __shared__ int s_key[NUM_PATHS];      // rank -> segment key (sorted)
    __shared__ int s_porder[NUM_PATHS];   // rank -> original path id
    __shared__ int s_off0[NUM_PATHS];     // rank -> idx0[p]*SEG_ELEMS
    __shared__ int s_out[NUM_PATHS];      // rank -> seg*SEG_ELEMS at boundary, else -1
    __shared__ int s_empty[NUM_SEG];      // seg offset to zero-fill, or -1
    __shared__ int s_best[3];             // packed splits near 16/32/48: (dist<<8)|r

    const int t    = threadIdx.x;
    const int w    = t >> 5;              // 0..3: quarter of the sorted path list
    const int lane = t & 31;
    const int b    = blockIdx.x;          // one batch row per CTA

    if (t < NUM_PATHS) s_idx2[t] = idx2[t];
    if (t >= NUM_PATHS && t < NUM_PATHS + 3) s_best[t - NUM_PATHS] = 0x7fffffff;
    __syncthreads();

    // Stage 1: stable counting-rank by idx2 + empty-segment scan (R12).
    if (t < NUM_PATHS) {
        const int key = s_idx2[t];
        int r = 0, nlater = 0;
        #pragma unroll 4
        for (int q = 0; q < NUM_PATHS; ++q) {
            const int kq = s_idx2[q];
            r      += (kq < key) | ((kq == key) & (q < t));
            nlater += (kq == key) & (q > t);
        }
        s_key[r]    = key;
        s_porder[r] = t;
        s_off0[r]   = idx0[t] * SEG_ELEMS;
        s_out[r]    = (nlater == 0) ? key * SEG_ELEMS : -1;
    } else if (t < NUM_PATHS + NUM_SEG) {
        const int s = t - NUM_PATHS;
        int c = 0;
        #pragma unroll 4
        for (int q = 0; q < NUM_PATHS; ++q) c += (s_idx2[q] == s);
        s_empty[s] = (c == 0) ? s * SEG_ELEMS : -1;
    }
    __syncthreads();

    // Stage 2a: parallel segment-aligned splits near ranks 16/32/48.
    if (t >= 1 && t <= NUM_PATHS) {
        const bool bnd = (t == NUM_PATHS) || (s_key[t] != s_key[t - 1]);
        if (bnd) {
            atomicMin(&s_best[0], (abs(t - 16) << 8) | t);
            atomicMin(&s_best[1], (abs(t - 32) << 8) | t);
            atomicMin(&s_best[2], (abs(t - 48) << 8) | t);
        }
    }
    // Stage 2b: build M — threads <64, one rank each.
    if (t < NUM_PATHS) {
        const int p = s_porder[t];
        const float* c   = coeff + p * 27;                       // [i][j][k]
        const float* x1b = x1 + (size_t)b * (NUM_SEG * D) + idx1[p] * D;
        const float j0 = x1b[0], j1 = x1b[1], j2 = x1b[2];
        float* Mr = &M[t * 12];
        #pragma unroll
        for (int i = 0; i < 3; ++i)
            #pragma unroll
            for (int k = 0; k < 3; ++k)
                Mr[i * 3 + k] =
                    j0 * c[i * 9 + 0 * 3 + k] +
                    j1 * c[i * 9 + 1 * 3 + k] +
                    j2 * c[i * 9 + 2 * 3 + k];
        Mr[9] = 0.f; Mr[10] = 0.f; Mr[11] = 0.f;
    }
    __syncthreads();

    int b1 = s_best[0] & 0xff;
    int b2 = s_best[1] & 0xff;
    int b3 = s_best[2] & 0xff;
    if (b2 < b1) b2 = b1;
    if (b3 < b2) b3 = b2;
    const int bounds[5] = { 0, b1, b2, b3, NUM_PATHS };
    const int qs = bounds[w];
    const int qe = bounds[w + 1];

    const float*  x0b  = x0  + (size_t)b * ROW_ELEMS;
    float*        outb = out + (size_t)b * ROW_ELEMS;
    const float4* M4   = (const float4*)M;

    const uint32_t ring_base =
        (uint32_t)__cvta_generic_to_shared(&ring[w][0][0]) + lane * 16;

    // Issue stage copy for rank q into ring slot (3x16B per lane, each
    // cp.async instr covers a contiguous 512B warp footprint). Empty commit
    // past the end keeps the group-count invariant.
    auto issue = [&](int q, int slot) {
        if (q < qe) {
            const char* src = (const char*)(x0b + s_off0[q]) + lane * 16;
            const uint32_t dst = ring_base + slot * SEG_BYTES;
            cpasync16(dst,        src);
            cpasync16(dst +  512, src +  512);
            cpasync16(dst + 1024, src + 1024);
        }
        CP_COMMIT();
    };

    #pragma unroll
    for (int i = 0; i < STAGES; ++i) issue(qs + i, i);

    float acc[12];
    #pragma unroll
    for (int i = 0; i < 12; ++i) acc[i] = 0.f;

    for (int q = qs; q < qe; ++q) {
        CP_WAIT3();                       // stage for q is complete
        __syncwarp();                     // cross-lane visibility
        const int slot = (q - qs) & (STAGES - 1);

        const float4* xs = (const float4*)&ring[w][slot][lane * 12];
        const float4 v0 = xs[0];
        const float4 v1 = xs[1];
        const float4 v2 = xs[2];

        issue(q + STAGES, slot);          // refill the slot just consumed

        const float a[12] = { v0.x, v0.y, v0.z, v0.w,
                              v1.x, v1.y, v1.z, v1.w,
                              v2.x, v2.y, v2.z, v2.w };
        const float4 q0 = M4[q * 3 + 0];
        const float4 q1 = M4[q * 3 + 1];
        const float4 q2 = M4[q * 3 + 2];
        const float m[9] = { q0.x, q0.y, q0.z, q0.w,
                             q1.x, q1.y, q1.z, q1.w, q2.x };

        #pragma unroll
        for (int u = 0; u < 4; ++u)
            #pragma unroll
            for (int k = 0; k < 3; ++k)
                acc[u * 3 + k] += a[u * 3 + 0] * m[0 + k]
                                + a[u * 3 + 1] * m[3 + k]
                                + a[u * 3 + 2] * m[6 + k];

        const int oo = s_out[q];          // warp-uniform branch
        if (oo >= 0) {
            float4* o = (float4*)(outb + oo) + lane * 3;
            o[0] = make_float4(acc[0], acc[1], acc[2],  acc[3]);
            o[1] = make_float4(acc[4], acc[5], acc[6],  acc[7]);
            o[2] = make_float4(acc[8], acc[9], acc[10], acc[11]);
            #pragma unroll
            for (int i = 0; i < 12; ++i) acc[i] = 0.f;
        }
    }

    // Zero-fill empty segments (poisoned output); spread across 4 warps.
    const float4 z = make_float4(0.f, 0.f, 0.f, 0.f);
    #pragma unroll
    for (int s = 0; s < NUM_SEG; ++s) {
        const int eo = s_empty[s];
        if (eo >= 0 && (s & 3) == w) {
            float4* o = (float4*)(outb + eo) + lane * 3;
            o[0] = z; o[1] = z; o[2] = z;
        }
    }
}

extern "C" void kernel_launch(void* const* d_in, const int* in_sizes, int n_in,
                              void* d_out, int out_size)
{
    const float* x0    = (const float*)d_in[0];  // (2048, 12288)
    const float* x1    = (const float*)d_in[1];  // (2048, 96)
    const float* coeff = (const float*)d_in[2];  // (64, 27)
    const int*   idx0  = (const int*)d_in[3];
    const int*   idx1  = (const int*)d_in[4];
    const int*   idx2  = (const int*)d_in[5];
    float*       out   = (float*)d_out;          // (2048, 12288)

    const int batch = in_sizes[0] / ROW_ELEMS;   // 2048
    ftp3_main<<<batch, 128>>>(x0, x1, coeff, idx0, idx1, idx2, out);
}